// round 13
// baseline (speedup 1.0000x reference)
#include <cuda_runtime.h>

#define H 512
#define W 512
#define NPTS 12
#define NMAPS 16          // B(8) * 2 groups
#define TSAT 21.0f        // d >= TSAT -> tanh(2*sqrt(d)) == 1.0f exactly in fp32
#define PCOL4 13          // float4 columns per patch window
#define PROWS 47          // rows per patch window
#define PUNITS (PROWS * PCOL4)          // 611 float4 units per patch
#define SUBS 20                          // 20 x 32 lanes = 640 >= 611
#define NPATCH_BLK (NMAPS * NPTS * SUBS) // 3840

// tanh(2*sqrt(d)) = 1 - 2/(exp(4*sqrt(d)) + 1); only called with d < TSAT.
__device__ __forceinline__ float fast_out(float d) {
    float s, t, r;
    asm("sqrt.approx.f32 %0, %1;" : "=f"(s) : "f"(d));
    float e = 5.770780163555852f * s;          // 4*log2(e)*sqrt(d)
    asm("ex2.approx.f32 %0, %1;" : "=f"(t) : "f"(e));
    float tp1 = t + 1.0f;
    asm("rcp.approx.f32 %0, %1;" : "=f"(r) : "f"(tp1));
    return fmaf(-2.0f, r, 1.0f);
}

// ---- Kernel 1: pure fill (proven ~4.3us). 2048 blocks x 256 threads,
// 2 float4/thread. Block 0 prefetches coords into L2 for the patch kernel.
__global__ __launch_bounds__(256) void fill_kernel(
    float4* __restrict__ out, const float4* __restrict__ coords4)
{
    const float4 one = make_float4(1.0f, 1.0f, 1.0f, 1.0f);
    unsigned idx = blockIdx.x * 512u + threadIdx.x;
    out[idx]       = one;
    out[idx + 256] = one;
    if (blockIdx.x == 0 && threadIdx.x < (NMAPS * NPTS * 3 + 3) / 4) {
        float4 v = __ldg(coords4 + threadIdx.x);
        if (v.x < -1.0e30f) ((float*)out)[0] = v.y;   // never taken; keeps the load
    }
}

// ---- Kernel 2: patch. 3840 blocks x 32 threads (1 warp), 1 float4/lane.
// No smem, no barriers. Every lane loads the map's 36 coord floats via
// 9 warp-uniform LDG.128 (L2-hot broadcast) into registers, computes the
// exact 12-point min + tanh for its 4 pixels, stores. Overlapping patches
// write byte-identical values.
__global__ __launch_bounds__(32) void patch_kernel(
    const float4* __restrict__ coords4,   // (8,24,3) viewed as float4[144]
    float* __restrict__ out)              // (8, 2, 512, 512)
{
    const int blk  = blockIdx.x;
    const int pid  = blk / SUBS;                  // 0..191
    const int sub  = blk - pid * SUBS;            // 0..19
    const int m    = pid / NPTS;                  // map 0..15
    const int p    = pid - m * NPTS;              // point 0..11
    const int lane = threadIdx.x;

    // All 36 floats of this map's 12 points -> registers (uniform-address LDG).
    float sc[36];
    const float4* base = coords4 + m * 9;
#pragma unroll
    for (int i = 0; i < 9; i++) {
        float4 v = __ldg(base + i);
        sc[i * 4 + 0] = v.x; sc[i * 4 + 1] = v.y;
        sc[i * 4 + 2] = v.z; sc[i * 4 + 3] = v.w;
    }

    const float yp = sc[p * 3 + 0];
    const float xp = sc[p * 3 + 1];
    if (fmaxf(yp, xp) < 0.0f) return;             // invalid anchor: no patch

    const int u = sub * 32 + lane;
    if (u >= PUNITS) return;

    const int iy = (int)floorf(yp);
    const int ix = (int)floorf(xp);
    const int r  = iy - 23 + u / PCOL4;
    const int c  = ((ix - 23) & ~3) + (u % PCOL4) * 4;
    if (r < 0 || r >= H || c < 0 || c > W - 4) return;

    const float rf  = (float)r;
    const float cs0 = (float)c * 0.2f;
    const float cs1 = (float)(c + 1) * 0.2f;
    const float cs2 = (float)(c + 2) * 0.2f;
    const float cs3 = (float)(c + 3) * 0.2f;

    float m0 = 1.0e6f, m1 = 1.0e6f, m2 = 1.0e6f, m3 = 1.0e6f;
#pragma unroll
    for (int j = 0; j < NPTS; j++) {
        float y = sc[j * 3 + 0];
        float x = sc[j * 3 + 1];
        float bse = (fmaxf(y, x) < 0.0f) ? 1000000.0f : 0.0f;
        float t = (rf - y) * 0.2f;
        float a = fmaf(t, t, bse);
        float nx = -x * 0.2f;
        float d0 = cs0 + nx, d1 = cs1 + nx, d2 = cs2 + nx, d3 = cs3 + nx;
        m0 = fminf(m0, fmaf(d0, d0, a));
        m1 = fminf(m1, fmaf(d1, d1, a));
        m2 = fminf(m2, fmaf(d2, d2, a));
        m3 = fminf(m3, fmaf(d3, d3, a));
    }

    float4 v;
    v.x = (m0 < TSAT) ? fast_out(m0) : 1.0f;
    v.y = (m1 < TSAT) ? fast_out(m1) : 1.0f;
    v.z = (m2 < TSAT) ? fast_out(m2) : 1.0f;
    v.w = (m3 < TSAT) ? fast_out(m3) : 1.0f;

    *(float4*)(out + ((size_t)m * H + r) * W + c) = v;
}

extern "C" void kernel_launch(void* const* d_in, const int* in_sizes, int n_in,
                              void* d_out, int out_size)
{
    const float* coords = nullptr;
    for (int i = 0; i < n_in; i++) {
        if (in_sizes[i] == 8 * 24 * 3) { coords = (const float*)d_in[i]; break; }
    }
    if (!coords) coords = (const float*)d_in[n_in - 1];

    float* out = (float*)d_out;

    fill_kernel<<<2048, 256>>>((float4*)out, (const float4*)coords);
    patch_kernel<<<NPATCH_BLK, 32>>>((const float4*)coords, out);
}